// round 6
// baseline (speedup 1.0000x reference)
#include <cuda_runtime.h>
#include <cuda_bf16.h>
#include <math.h>
#include <cstdint>

constexpr int kN = 8192;   // num_elem
constexpr int kD = 1024;   // input_size
constexpr int kH = 1024;   // hidden_size
constexpr int kG = 2048;   // num_groups

// ---------------- device scratch ----------------
__device__ float g_u[kD];
__device__ float g_cs[kD];
__device__ float g_S;
__device__ float g_t[kH];
__device__ float g_w2[kD];
__device__ float g_c;
__device__ float g_s[kN];
__device__ float g_e[kN];
__device__ float g_vcs[kH];
__device__ float g_Z[kG];
__device__ __nv_bfloat16 g_inh[(size_t)kN * kD];   // input hi   [n][d]
__device__ __nv_bfloat16 g_inl[(size_t)kN * kD];   // input lo
__device__ __nv_bfloat16 g_wvh[(size_t)kH * kD];   // Wv hi      [h][d]
__device__ __nv_bfloat16 g_wvl[(size_t)kH * kD];   // Wv lo
__device__ __nv_bfloat16 g_veh[(size_t)kN * kH];   // e*v hi     [n][h]
__device__ __nv_bfloat16 g_vel[(size_t)kN * kH];   // e*v lo
__device__ __nv_bfloat16 g_mT[(size_t)kG * kN];    // mask^T bf16 0/1

// ---------------- mma helpers (validated in R2/R5) ----------------
__device__ __forceinline__ void ldsm4(unsigned& r0, unsigned& r1, unsigned& r2, unsigned& r3,
                                      const void* p) {
    unsigned a = (unsigned)__cvta_generic_to_shared(p);
    asm volatile("ldmatrix.sync.aligned.m8n8.x4.shared.b16 {%0,%1,%2,%3}, [%4];"
                 : "=r"(r0), "=r"(r1), "=r"(r2), "=r"(r3) : "r"(a));
}
__device__ __forceinline__ void ldsm4t(unsigned& r0, unsigned& r1, unsigned& r2, unsigned& r3,
                                       const void* p) {
    unsigned a = (unsigned)__cvta_generic_to_shared(p);
    asm volatile("ldmatrix.sync.aligned.m8n8.x4.trans.shared.b16 {%0,%1,%2,%3}, [%4];"
                 : "=r"(r0), "=r"(r1), "=r"(r2), "=r"(r3) : "r"(a));
}
__device__ __forceinline__ void mma_bf16(float* c, const unsigned* a, unsigned b0, unsigned b1) {
    asm volatile("mma.sync.aligned.m16n8k16.row.col.f32.bf16.bf16.f32 "
                 "{%0,%1,%2,%3},{%4,%5,%6,%7},{%8,%9},{%0,%1,%2,%3};"
                 : "+f"(c[0]), "+f"(c[1]), "+f"(c[2]), "+f"(c[3])
                 : "r"(a[0]), "r"(a[1]), "r"(a[2]), "r"(a[3]), "r"(b0), "r"(b1));
}
__device__ __forceinline__ void cp_async16(uint32_t dst, const void* src) {
    asm volatile("cp.async.cg.shared.global [%0], [%1], 16;" :: "r"(dst), "l"(src) : "memory");
}
__device__ __forceinline__ void cp_commit() {
    asm volatile("cp.async.commit_group;" ::: "memory");
}
template <int Nn>
__device__ __forceinline__ void cp_wait() {
    asm volatile("cp.async.wait_group %0;" :: "n"(Nn) : "memory");
}
__device__ __forceinline__ uint32_t smem_u32(const void* p) {
    return (uint32_t)__cvta_generic_to_shared(p);
}

extern __shared__ __align__(128) char dynsmem[];

// ---------------- init ----------------
__global__ void k_init() {
    int idx = blockIdx.x * 256 + threadIdx.x;
    if (idx < kD) { g_u[idx] = 0.f; g_w2[idx] = 0.f; g_cs[idx] = 0.f; }
    if (idx < kG) g_Z[idx] = 0.f;
    if (idx == 0) g_S = 0.f;
}

// ---------------- fp32 -> bf16 hi/lo split ----------------
__global__ void k_split(const float4* __restrict__ src, __nv_bfloat16* __restrict__ hi,
                        __nv_bfloat16* __restrict__ lo) {
    size_t i = (size_t)blockIdx.x * 256 + threadIdx.x;
    float4 x = src[i];
    __nv_bfloat16 h0 = __float2bfloat16(x.x), h1 = __float2bfloat16(x.y);
    __nv_bfloat16 h2 = __float2bfloat16(x.z), h3 = __float2bfloat16(x.w);
    __nv_bfloat162 hv0; hv0.x = h0; hv0.y = h1;
    __nv_bfloat162 hv1; hv1.x = h2; hv1.y = h3;
    __nv_bfloat162 lv0, lv1;
    lv0.x = __float2bfloat16(x.x - __bfloat162float(h0));
    lv0.y = __float2bfloat16(x.y - __bfloat162float(h1));
    lv1.x = __float2bfloat16(x.z - __bfloat162float(h2));
    lv1.y = __float2bfloat16(x.w - __bfloat162float(h3));
    *(__nv_bfloat162*)(hi + 4 * i)     = hv0;
    *(__nv_bfloat162*)(hi + 4 * i + 2) = hv1;
    *(__nv_bfloat162*)(lo + 4 * i)     = lv0;
    *(__nv_bfloat162*)(lo + 4 * i + 2) = lv1;
}

// ---------------- mask transpose: [N,G] int -> [G,N] bf16 ----------------
__global__ void k_maskT(const int* __restrict__ mask) {
    __shared__ float t[32][33];
    int gb = blockIdx.x * 32, nb = blockIdx.y * 32;
    int tx = threadIdx.x, ty = threadIdx.y;     // (32,8)
    #pragma unroll
    for (int r = 0; r < 4; r++)
        t[ty + r * 8][tx] = mask[(size_t)(nb + ty + r * 8) * kG + gb + tx] ? 1.f : 0.f;
    __syncthreads();
    #pragma unroll
    for (int r = 0; r < 4; r++)
        g_mT[(size_t)(gb + ty + r * 8) * kN + nb + tx] = __float2bfloat16(t[tx][ty + r * 8]);
}

// ---------------- u = input^T @ sw ; cs = colsum(input) ; S = sum(sw) ----------------
__global__ void k_u(const float* __restrict__ inp, const float* __restrict__ sw) {
    int d  = blockIdx.x * 256 + threadIdx.x;
    int n0 = blockIdx.y * (kN / 32);
    float acc = 0.f, acc2 = 0.f;
    #pragma unroll 4
    for (int n = n0; n < n0 + kN / 32; n++) {
        float x = inp[(size_t)n * kD + d];
        acc += x * sw[n];
        acc2 += x;
    }
    atomicAdd(&g_u[d], acc);
    atomicAdd(&g_cs[d], acc2);
    if (blockIdx.x == 0) {
        __shared__ float red[256];
        red[threadIdx.x] = sw[n0 + threadIdx.x];
        __syncthreads();
        for (int s = 128; s > 0; s >>= 1) {
            if (threadIdx.x < s) red[threadIdx.x] += red[threadIdx.x + s];
            __syncthreads();
        }
        if (threadIdx.x == 0) atomicAdd(&g_S, red[0]);
    }
}

// ---------------- t = Wk @ u + bk * S ----------------
__global__ void k_t(const float* __restrict__ Wk, const float* __restrict__ bk) {
    int warp = threadIdx.x >> 5, lane = threadIdx.x & 31;
    int row = blockIdx.x * 8 + warp;
    const float* w = Wk + (size_t)row * kD;
    float acc = 0.f;
    #pragma unroll 8
    for (int k = lane; k < kD; k += 32) acc += w[k] * g_u[k];
    #pragma unroll
    for (int o = 16; o; o >>= 1) acc += __shfl_xor_sync(0xffffffffu, acc, o);
    if (lane == 0) g_t[row] = acc + bk[row] * g_S;
}

// ---------------- w2 = Wq^T @ t ; c = bq.t + score_b ----------------
__global__ void k_w2c(const float* __restrict__ Wq, const float* __restrict__ bq,
                      const float* __restrict__ score_b) {
    int b = blockIdx.x;
    if (b < 32) {
        int d  = (b & 3) * 256 + threadIdx.x;
        int h0 = (b >> 2) * 128;
        float acc = 0.f;
        #pragma unroll 4
        for (int h = h0; h < h0 + 128; h++)
            acc += Wq[(size_t)h * kD + d] * g_t[h];
        atomicAdd(&g_w2[d], acc);
    } else {
        __shared__ float red[256];
        float acc = 0.f;
        for (int h = threadIdx.x; h < kH; h += 256) acc += bq[h] * g_t[h];
        red[threadIdx.x] = acc;
        __syncthreads();
        for (int s = 128; s > 0; s >>= 1) {
            if (threadIdx.x < s) red[threadIdx.x] += red[threadIdx.x + s];
            __syncthreads();
        }
        if (threadIdx.x == 0) g_c = red[0] + score_b[0];
    }
}

// ---------------- s[n] = input[n,:].w2 + c ----------------
__global__ void k_s(const float* __restrict__ inp) {
    int warp = threadIdx.x >> 5, lane = threadIdx.x & 31;
    int row = blockIdx.x * 8 + warp;
    const float* r = inp + (size_t)row * kD;
    float acc = 0.f;
    #pragma unroll 8
    for (int k = lane; k < kD; k += 32) acc += r[k] * g_w2[k];
    #pragma unroll
    for (int o = 16; o; o >>= 1) acc += __shfl_xor_sync(0xffffffffu, acc, o);
    if (lane == 0) g_s[row] = acc + g_c;
}

// ---------------- e = exp(s - smax) ----------------
__global__ void k_e() {
    __shared__ float red[1024];
    __shared__ float smax;
    float m = -INFINITY;
    for (int i = threadIdx.x; i < kN; i += 1024) m = fmaxf(m, g_s[i]);
    red[threadIdx.x] = m;
    __syncthreads();
    for (int s = 512; s > 0; s >>= 1) {
        if (threadIdx.x < s) red[threadIdx.x] = fmaxf(red[threadIdx.x], red[threadIdx.x + s]);
        __syncthreads();
    }
    if (threadIdx.x == 0) smax = red[0];
    __syncthreads();
    float mx = smax;
    for (int i = threadIdx.x; i < kN; i += 1024) g_e[i] = expf(g_s[i] - mx);
}

// ---------------- vcs[h] = Wv[h,:].cs + N*bv[h] ----------------
__global__ void k_vcs(const float* __restrict__ Wv, const float* __restrict__ bv) {
    int warp = threadIdx.x >> 5, lane = threadIdx.x & 31;
    int row = blockIdx.x * 8 + warp;
    const float* w = Wv + (size_t)row * kD;
    float acc = 0.f;
    #pragma unroll 8
    for (int k = lane; k < kD; k += 32) acc += w[k] * g_cs[k];
    #pragma unroll
    for (int o = 16; o; o >>= 1) acc += __shfl_xor_sync(0xffffffffu, acc, o);
    if (lane == 0) g_vcs[row] = acc + (float)kN * bv[row];
}

// ================= GEMM 1: ve = e*(input @ Wv^T + bv), pipelined mma.sync =================
constexpr int V_STAGES = 3;
constexpr int V_TS = 128 * 40;                  // tile elems (padded rows of 40 bf16)
constexpr int V_STG_E = 4 * V_TS;               // Ah, Al, Bh, Bl per stage (elems)
constexpr int V_SMEM = V_STAGES * V_STG_E * 2;  // 122880 bytes
constexpr int V_CHUNKS = kD / 32;               // 32

__global__ __launch_bounds__(256, 1) void k_v_mma(const float* __restrict__ bv) {
    __nv_bfloat16* sm = (__nv_bfloat16*)dynsmem;
    const int tid = threadIdx.x, lane = tid & 31, wid = tid >> 5;
    const int wm = (wid & 3) * 32, wn = (wid >> 2) * 64;
    const int n0 = blockIdx.x * 128;   // h tile
    const int m0 = blockIdx.y * 128;   // elem tile
    const int lrow = tid >> 1, lcol = (tid & 1) * 16;
    const uint32_t sbase = smem_u32(sm);

    const __nv_bfloat16* Ah = g_inh + (size_t)(m0 + lrow) * kD + lcol;
    const __nv_bfloat16* Al = g_inl + (size_t)(m0 + lrow) * kD + lcol;
    const __nv_bfloat16* Bh = g_wvh + (size_t)(n0 + lrow) * kD + lcol;
    const __nv_bfloat16* Bl = g_wvl + (size_t)(n0 + lrow) * kD + lcol;
    const uint32_t dst0 = sbase + (lrow * 40 + lcol) * 2;

    auto load_chunk = [&](int chunk, int stg) {
        uint32_t d = dst0 + stg * V_STG_E * 2;
        int ko = chunk * 32;
        cp_async16(d,                     Ah + ko);
        cp_async16(d + 16,                Ah + ko + 8);
        cp_async16(d + V_TS * 2,          Al + ko);
        cp_async16(d + V_TS * 2 + 16,     Al + ko + 8);
        cp_async16(d + 2 * V_TS * 2,      Bh + ko);
        cp_async16(d + 2 * V_TS * 2 + 16, Bh + ko + 8);
        cp_async16(d + 3 * V_TS * 2,      Bl + ko);
        cp_async16(d + 3 * V_TS * 2 + 16, Bl + ko + 8);
    };

    float acc[2][8][4];
    #pragma unroll
    for (int i = 0; i < 2; i++)
        #pragma unroll
        for (int j = 0; j < 8; j++)
            #pragma unroll
            for (int q = 0; q < 4; q++) acc[i][j][q] = 0.f;

    #pragma unroll
    for (int s = 0; s < V_STAGES - 1; ++s) { load_chunk(s, s); cp_commit(); }

    for (int i = 0; i < V_CHUNKS; ++i) {
        cp_wait<V_STAGES - 2>();
        __syncthreads();
        const int stg = i % V_STAGES;
        __nv_bfloat16 (*SAh)[40] = (__nv_bfloat16(*)[40])(sm + stg * V_STG_E);
        __nv_bfloat16 (*SAl)[40] = (__nv_bfloat16(*)[40])(sm + stg * V_STG_E + V_TS);
        __nv_bfloat16 (*SBh)[40] = (__nv_bfloat16(*)[40])(sm + stg * V_STG_E + 2 * V_TS);
        __nv_bfloat16 (*SBl)[40] = (__nv_bfloat16(*)[40])(sm + stg * V_STG_E + 3 * V_TS);
        // hoist ALL fragment loads for the chunk before the MMA run
        unsigned ah[2][2][4], al[2][2][4], bh[2][4][4], bl[2][4][4];
        #pragma unroll
        for (int kh = 0; kh < 2; kh++) {
            int kk = kh * 16;
            #pragma unroll
            for (int im = 0; im < 2; im++) {
                ldsm4(ah[kh][im][0], ah[kh][im][1], ah[kh][im][2], ah[kh][im][3],
                      &SAh[wm + im * 16 + (lane & 15)][kk + (lane >> 4) * 8]);
                ldsm4(al[kh][im][0], al[kh][im][1], al[kh][im][2], al[kh][im][3],
                      &SAl[wm + im * 16 + (lane & 15)][kk + (lane >> 4) * 8]);
            }
            #pragma unroll
            for (int jn = 0; jn < 4; jn++) {
                ldsm4(bh[kh][jn][0], bh[kh][jn][1], bh[kh][jn][2], bh[kh][jn][3],
                      &SBh[wn + jn * 16 + (lane & 7) + ((lane >> 4) << 3)]
                          [kk + ((lane >> 3) & 1) * 8]);
                ldsm4(bl[kh][jn][0], bl[kh][jn][1], bl[kh][jn][2], bl[kh][jn][3],
                      &SBl[wn + jn * 16 + (lane & 7) + ((lane >> 4) << 3)]
                          [kk + ((lane >> 3) & 1) * 8]);
            }
        }
        #pragma unroll
        for (int kh = 0; kh < 2; kh++)
            #pragma unroll
            for (int im = 0; im < 2; im++)
                #pragma unroll
                for (int j = 0; j < 8; j++) {
                    mma_bf16(acc[im][j], ah[kh][im], bh[kh][j >> 1][(j & 1) * 2],
                             bh[kh][j >> 1][(j & 1) * 2 + 1]);
                    mma_bf16(acc[im][j], ah[kh][im], bl[kh][j >> 1][(j & 1) * 2],
                             bl[kh][j >> 1][(j & 1) * 2 + 1]);
                    mma_bf16(acc[im][j], al[kh][im], bh[kh][j >> 1][(j & 1) * 2],
                             bh[kh][j >> 1][(j & 1) * 2 + 1]);
                }
        __syncthreads();
        int nx = i + V_STAGES - 1;
        if (nx < V_CHUNKS) load_chunk(nx, nx % V_STAGES);
        cp_commit();
    }

    // epilogue: add bias, scale by e[m], split to bf16 hi/lo
    const int gr = lane >> 2, gc = (lane & 3) * 2;
    #pragma unroll
    for (int im = 0; im < 2; im++) {
        #pragma unroll
        for (int r = 0; r < 2; r++) {
            int m = m0 + wm + im * 16 + gr + r * 8;
            float ev = g_e[m];
            #pragma unroll
            for (int j = 0; j < 8; j++) {
                int h = n0 + wn + j * 8 + gc;
                float x0 = (acc[im][j][r * 2 + 0] + bv[h])     * ev;
                float x1 = (acc[im][j][r * 2 + 1] + bv[h + 1]) * ev;
                __nv_bfloat16 h0 = __float2bfloat16(x0);
                __nv_bfloat16 h1 = __float2bfloat16(x1);
                __nv_bfloat162 hv; hv.x = h0; hv.y = h1;
                __nv_bfloat162 lv;
                lv.x = __float2bfloat16(x0 - __bfloat162float(h0));
                lv.y = __float2bfloat16(x1 - __bfloat162float(h1));
                *(__nv_bfloat162*)&g_veh[(size_t)m * kH + h] = hv;
                *(__nv_bfloat162*)&g_vel[(size_t)m * kH + h] = lv;
            }
        }
    }
}

// ================= GEMM 2: out = (mT @ ve) / Z, 128x64 tiles, 2 CTAs/SM =================
constexpr int A_STAGES = 4;
constexpr int A_ATS = 128 * 40;                  // A tile: 128g x 32k (pad 40)
constexpr int A_BTS = 32 * 72;                   // B tile: 32k x 64h (pad 72)
constexpr int A_STG_E = A_ATS + 2 * A_BTS;       // 9728 elems
constexpr int A_SMEM = A_STAGES * A_STG_E * 2;   // 77824 bytes
constexpr int A_CHUNKS = kN / 32;                // 256

__global__ __launch_bounds__(256, 2) void k_agg_mma(float* __restrict__ out) {
    __nv_bfloat16* sm = (__nv_bfloat16*)dynsmem;
    const int tid = threadIdx.x, lane = tid & 31, wid = tid >> 5;
    const int wm = (wid & 3) * 32, wn = (wid >> 2) * 32;   // 4x2 warp grid
    const int h0 = blockIdx.x * 64;
    const int g0 = blockIdx.y * 128;
    const int lrow = tid >> 1, lcol = (tid & 1) * 16;   // A indices (128x32)
    const int brow = tid >> 3, bcol = (tid & 7) * 8;    // B indices (32x64)
    const uint32_t sbase = smem_u32(sm);

    const __nv_bfloat16* Ag  = g_mT  + (size_t)(g0 + lrow) * kN + lcol;
    const __nv_bfloat16* Bhp = g_veh + (size_t)brow * kH + h0 + bcol;
    const __nv_bfloat16* Blp = g_vel + (size_t)brow * kH + h0 + bcol;
    const uint32_t adst0 = sbase + (lrow * 40 + lcol) * 2;
    const uint32_t bdst0 = sbase + A_ATS * 2 + (brow * 72 + bcol) * 2;

    auto load_chunk = [&](int chunk, int stg) {
        uint32_t ad = adst0 + stg * A_STG_E * 2;
        uint32_t bd = bdst0 + stg * A_STG_E * 2;
        int ko = chunk * 32;
        cp_async16(ad,      Ag + ko);
        cp_async16(ad + 16, Ag + ko + 8);
        size_t boff = (size_t)ko * kH;
        cp_async16(bd,             Bhp + boff);
        cp_async16(bd + A_BTS * 2, Blp + boff);
    };

    float acc[2][4][4];
    #pragma unroll
    for (int i = 0; i < 2; i++)
        #pragma unroll
        for (int j = 0; j < 4; j++)
            #pragma unroll
            for (int q = 0; q < 4; q++) acc[i][j][q] = 0.f;

    #pragma unroll
    for (int s = 0; s < A_STAGES - 1; ++s) { load_chunk(s, s); cp_commit(); }

    for (int i = 0; i < A_CHUNKS; ++i) {
        cp_wait<A_STAGES - 2>();
        __syncthreads();
        const int stg = i % A_STAGES;
        __nv_bfloat16 (*SA)[40]  = (__nv_bfloat16(*)[40])(sm + stg * A_STG_E);
        __nv_bfloat16 (*SBh)[72] = (__nv_bfloat16(*)[72])(sm + stg * A_STG_E + A_ATS);
        __nv_bfloat16 (*SBl)[72] = (__nv_bfloat16(*)[72])(sm + stg * A_STG_E + A_ATS + A_BTS);
        // hoist all fragment loads for the chunk
        unsigned a[2][2][4], bh[2][2][4], bl[2][2][4];
        #pragma unroll
        for (int kh = 0; kh < 2; kh++) {
            int kk = kh * 16;
            #pragma unroll
            for (int im = 0; im < 2; im++)
                ldsm4(a[kh][im][0], a[kh][im][1], a[kh][im][2], a[kh][im][3],
                      &SA[wm + im * 16 + (lane & 15)][kk + (lane >> 4) * 8]);
            #pragma unroll
            for (int jn = 0; jn < 2; jn++) {
                ldsm4t(bh[kh][jn][0], bh[kh][jn][1], bh[kh][jn][2], bh[kh][jn][3],
                       &SBh[kk + (lane & 7) + ((lane >> 3) & 1) * 8]
                           [wn + jn * 16 + (lane >> 4) * 8]);
                ldsm4t(bl[kh][jn][0], bl[kh][jn][1], bl[kh][jn][2], bl[kh][jn][3],
                       &SBl[kk + (lane & 7) + ((lane >> 3) & 1) * 8]
                           [wn + jn * 16 + (lane >> 4) * 8]);
            }
        }
        #pragma unroll
        for (int kh = 0; kh < 2; kh++)
            #pragma unroll
            for (int im = 0; im < 2; im++)
                #pragma unroll
                for (int j = 0; j < 4; j++) {
                    mma_bf16(acc[im][j], a[kh][im], bh[kh][j >> 1][(j & 1) * 2],
                             bh[kh][j >> 1][(j & 1) * 2 + 1]);
                    mma_bf16(acc[im][j], a[kh][im], bl[kh][j >> 1][(j & 1) * 2],
                             bl[kh][j >> 1][(j & 1) * 2 + 1]);
                }
        __syncthreads();
        int nx = i + A_STAGES - 1;
        if (nx < A_CHUNKS) load_chunk(nx, nx % A_STAGES);
        cp_commit();
    }

    // epilogue: divide by Z (or fallback)
    const int gr = lane >> 2, gc = (lane & 3) * 2;
    #pragma unroll
    for (int im = 0; im < 2; im++) {
        #pragma unroll
        for (int r = 0; r < 2; r++) {
            int g = g0 + wm + im * 16 + gr + r * 8;
            float Zv = g_Z[g];
            if (Zv > 0.f) {
                float rZ = 1.f / Zv;
                #pragma unroll
                for (int j = 0; j < 4; j++) {
                    int h = h0 + wn + j * 8 + gc;
                    float2 o;
                    o.x = acc[im][j][r * 2 + 0] * rZ;
                    o.y = acc[im][j][r * 2 + 1] * rZ;
                    *(float2*)&out[(size_t)g * kH + h] = o;
                }
            } else {
                const float invn = 1.f / (float)kN;
                #pragma unroll
                for (int j = 0; j < 4; j++) {
                    int h = h0 + wn + j * 8 + gc;
                    float2 o;
                    o.x = g_vcs[h] * invn;
                    o.y = g_vcs[h + 1] * invn;
                    *(float2*)&out[(size_t)g * kH + h] = o;
                }
            }
        }
    }
}

// ---------------- Z[g] = sum_n maskT[g,n]*e[n] ----------------
__global__ void k_Z2() {
    int g = blockIdx.x * 8 + (threadIdx.x >> 5);
    int lane = threadIdx.x & 31;
    const __nv_bfloat16* mrow = g_mT + (size_t)g * kN;
    float acc = 0.f;
    for (int n = lane * 8; n < kN; n += 32 * 8) {
        uint4 mv = *(const uint4*)(mrow + n);
        float4 e0 = *(const float4*)(g_e + n);
        float4 e1 = *(const float4*)(g_e + n + 4);
        const __nv_bfloat162* mp = (const __nv_bfloat162*)&mv;
        float2 m0 = __bfloat1622float2(mp[0]);
        float2 m1 = __bfloat1622float2(mp[1]);
        float2 m2 = __bfloat1622float2(mp[2]);
        float2 m3 = __bfloat1622float2(mp[3]);
        acc += m0.x * e0.x + m0.y * e0.y + m1.x * e0.z + m1.y * e0.w
             + m2.x * e1.x + m2.y * e1.y + m3.x * e1.z + m3.y * e1.w;
    }
    #pragma unroll
    for (int o = 16; o; o >>= 1) acc += __shfl_xor_sync(0xffffffffu, acc, o);
    if (lane == 0) g_Z[g] = acc;
}

// ---------------- attn[g,n] = maskT[g,n]*e[n]/Z[g] (or 1/N fallback) ----------------
__global__ void k_attn2(float* __restrict__ attn) {
    int g = blockIdx.x;
    float Zv = g_Z[g];
    bool fb = !(Zv > 0.f);
    float rZ = fb ? 0.f : 1.f / Zv;
    const float invn = 1.f / (float)kN;
    const __nv_bfloat16* mrow = g_mT + (size_t)g * kN;
    float* arow = attn + (size_t)g * kN;
    for (int n = threadIdx.x * 8; n < kN; n += 256 * 8) {
        uint4 mv = *(const uint4*)(mrow + n);
        float4 e0 = *(const float4*)(g_e + n);
        float4 e1 = *(const float4*)(g_e + n + 4);
        const __nv_bfloat162* mp = (const __nv_bfloat162*)&mv;
        float2 m0 = __bfloat1622float2(mp[0]);
        float2 m1 = __bfloat1622float2(mp[1]);
        float2 m2 = __bfloat1622float2(mp[2]);
        float2 m3 = __bfloat1622float2(mp[3]);
        float4 o0, o1;
        if (fb) {
            o0.x = o0.y = o0.z = o0.w = invn;
            o1 = o0;
        } else {
            o0.x = m0.x * e0.x * rZ; o0.y = m0.y * e0.y * rZ;
            o0.z = m1.x * e0.z * rZ; o0.w = m1.y * e0.w * rZ;
            o1.x = m2.x * e1.x * rZ; o1.y = m2.y * e1.y * rZ;
            o1.z = m3.x * e1.z * rZ; o1.w = m3.y * e1.w * rZ;
        }
        *(float4*)(arow + n)     = o0;
        *(float4*)(arow + n + 4) = o1;
    }
}

// ---------------- host launcher ----------------
extern "C" void kernel_launch(void* const* d_in, const int* in_sizes, int n_in,
                              void* d_out, int out_size) {
    const float* input = (const float*)d_in[0];
    const float* Wq    = (const float*)d_in[1];
    const float* bq    = (const float*)d_in[2];
    const float* Wk    = (const float*)d_in[3];
    const float* bk    = (const float*)d_in[4];
    const float* Wv    = (const float*)d_in[5];
    const float* bv    = (const float*)d_in[6];
    const float* sw    = (const float*)d_in[7];
    const float* sb    = (const float*)d_in[8];
    const int*   mask  = (const int*)d_in[9];
    float* out = (float*)d_out;

    __nv_bfloat16 *inh, *inl, *wvh, *wvl;
    cudaGetSymbolAddress((void**)&inh, g_inh);
    cudaGetSymbolAddress((void**)&inl, g_inl);
    cudaGetSymbolAddress((void**)&wvh, g_wvh);
    cudaGetSymbolAddress((void**)&wvl, g_wvl);

    static bool attr_set = false;
    if (!attr_set) {
        cudaFuncSetAttribute(k_v_mma, cudaFuncAttributeMaxDynamicSharedMemorySize, V_SMEM);
        cudaFuncSetAttribute(k_agg_mma, cudaFuncAttributeMaxDynamicSharedMemorySize, A_SMEM);
        attr_set = true;
    }

    k_init<<<8, 256>>>();
    k_split<<<(kN * kD) / 1024, 256>>>((const float4*)input, inh, inl);
    k_split<<<(kH * kD) / 1024, 256>>>((const float4*)Wv, wvh, wvl);
    k_maskT<<<dim3(kG / 32, kN / 32), dim3(32, 8)>>>(mask);
    k_u<<<dim3(4, 32), 256>>>(input, sw);
    k_t<<<128, 256>>>(Wk, bk);
    k_w2c<<<33, 256>>>(Wq, bq, sb);
    k_s<<<1024, 256>>>(input);
    k_e<<<1, 1024>>>();
    k_vcs<<<128, 256>>>(Wv, bv);
    k_v_mma<<<dim3(kH / 128, kN / 128), 256, V_SMEM>>>(bv);
    k_Z2<<<kG / 8, 256>>>();
    k_agg_mma<<<dim3(kH / 64, kG / 128), 256, A_SMEM>>>(out);
    k_attn2<<<kG, 256>>>(out + (size_t)kG * kH);
}

// round 7
// speedup vs baseline: 1.2157x; 1.2157x over previous
#include <cuda_runtime.h>
#include <cuda_bf16.h>
#include <cuda_fp16.h>
#include <math.h>
#include <cstdint>

constexpr int kN = 8192;   // num_elem
constexpr int kD = 1024;   // input_size
constexpr int kH = 1024;   // hidden_size
constexpr int kG = 2048;   // num_groups

// ---------------- device scratch ----------------
__device__ float g_u[kD];
__device__ float g_cs[kD];
__device__ float g_S;
__device__ float g_t[kH];
__device__ float g_w2[kD];
__device__ float g_c;
__device__ float g_s[kN];
__device__ float g_e[kN];
__device__ float g_vcs[kH];
__device__ float g_Z[kG];
__device__ __nv_bfloat16 g_inh[(size_t)kN * kD];   // input hi   [n][d]
__device__ __nv_bfloat16 g_inl[(size_t)kN * kD];   // input lo
__device__ __nv_bfloat16 g_wvh[(size_t)kH * kD];   // Wv hi      [h][d]
__device__ __nv_bfloat16 g_wvl[(size_t)kH * kD];   // Wv lo
__device__ __half g_vef[(size_t)kN * kH];          // e*v fp16   [n][h]
__device__ __half g_mT[(size_t)kG * kN];           // mask^T fp16 0/1

// ---------------- mma helpers ----------------
__device__ __forceinline__ void ldsm4(unsigned& r0, unsigned& r1, unsigned& r2, unsigned& r3,
                                      const void* p) {
    unsigned a = (unsigned)__cvta_generic_to_shared(p);
    asm volatile("ldmatrix.sync.aligned.m8n8.x4.shared.b16 {%0,%1,%2,%3}, [%4];"
                 : "=r"(r0), "=r"(r1), "=r"(r2), "=r"(r3) : "r"(a));
}
__device__ __forceinline__ void ldsm4t(unsigned& r0, unsigned& r1, unsigned& r2, unsigned& r3,
                                       const void* p) {
    unsigned a = (unsigned)__cvta_generic_to_shared(p);
    asm volatile("ldmatrix.sync.aligned.m8n8.x4.trans.shared.b16 {%0,%1,%2,%3}, [%4];"
                 : "=r"(r0), "=r"(r1), "=r"(r2), "=r"(r3) : "r"(a));
}
__device__ __forceinline__ void mma_bf16(float* c, const unsigned* a, unsigned b0, unsigned b1) {
    asm volatile("mma.sync.aligned.m16n8k16.row.col.f32.bf16.bf16.f32 "
                 "{%0,%1,%2,%3},{%4,%5,%6,%7},{%8,%9},{%0,%1,%2,%3};"
                 : "+f"(c[0]), "+f"(c[1]), "+f"(c[2]), "+f"(c[3])
                 : "r"(a[0]), "r"(a[1]), "r"(a[2]), "r"(a[3]), "r"(b0), "r"(b1));
}
__device__ __forceinline__ void mma_f16(float* c, const unsigned* a, unsigned b0, unsigned b1) {
    asm volatile("mma.sync.aligned.m16n8k16.row.col.f32.f16.f16.f32 "
                 "{%0,%1,%2,%3},{%4,%5,%6,%7},{%8,%9},{%0,%1,%2,%3};"
                 : "+f"(c[0]), "+f"(c[1]), "+f"(c[2]), "+f"(c[3])
                 : "r"(a[0]), "r"(a[1]), "r"(a[2]), "r"(a[3]), "r"(b0), "r"(b1));
}
__device__ __forceinline__ void cp_async16(uint32_t dst, const void* src) {
    asm volatile("cp.async.cg.shared.global [%0], [%1], 16;" :: "r"(dst), "l"(src) : "memory");
}
__device__ __forceinline__ void cp_commit() {
    asm volatile("cp.async.commit_group;" ::: "memory");
}
template <int Nn>
__device__ __forceinline__ void cp_wait() {
    asm volatile("cp.async.wait_group %0;" :: "n"(Nn) : "memory");
}
__device__ __forceinline__ uint32_t smem_u32(const void* p) {
    return (uint32_t)__cvta_generic_to_shared(p);
}

extern __shared__ __align__(128) char dynsmem[];

// ---------------- init ----------------
__global__ void k_init() {
    int idx = blockIdx.x * 256 + threadIdx.x;
    if (idx < kD) { g_u[idx] = 0.f; g_w2[idx] = 0.f; g_cs[idx] = 0.f; }
    if (idx < kG) g_Z[idx] = 0.f;
    if (idx == 0) g_S = 0.f;
}

// ---------------- fp32 -> bf16 hi/lo split ----------------
__global__ void k_split(const float4* __restrict__ src, __nv_bfloat16* __restrict__ hi,
                        __nv_bfloat16* __restrict__ lo) {
    size_t i = (size_t)blockIdx.x * 256 + threadIdx.x;
    float4 x = src[i];
    __nv_bfloat16 h0 = __float2bfloat16(x.x), h1 = __float2bfloat16(x.y);
    __nv_bfloat16 h2 = __float2bfloat16(x.z), h3 = __float2bfloat16(x.w);
    __nv_bfloat162 hv0; hv0.x = h0; hv0.y = h1;
    __nv_bfloat162 hv1; hv1.x = h2; hv1.y = h3;
    __nv_bfloat162 lv0, lv1;
    lv0.x = __float2bfloat16(x.x - __bfloat162float(h0));
    lv0.y = __float2bfloat16(x.y - __bfloat162float(h1));
    lv1.x = __float2bfloat16(x.z - __bfloat162float(h2));
    lv1.y = __float2bfloat16(x.w - __bfloat162float(h3));
    *(__nv_bfloat162*)(hi + 4 * i)     = hv0;
    *(__nv_bfloat162*)(hi + 4 * i + 2) = hv1;
    *(__nv_bfloat162*)(lo + 4 * i)     = lv0;
    *(__nv_bfloat162*)(lo + 4 * i + 2) = lv1;
}

// ---------------- mask transpose: [N,G] int -> [G,N] fp16 ----------------
__global__ void k_maskT(const int* __restrict__ mask) {
    __shared__ float t[32][33];
    int gb = blockIdx.x * 32, nb = blockIdx.y * 32;
    int tx = threadIdx.x, ty = threadIdx.y;     // (32,8)
    #pragma unroll
    for (int r = 0; r < 4; r++)
        t[ty + r * 8][tx] = mask[(size_t)(nb + ty + r * 8) * kG + gb + tx] ? 1.f : 0.f;
    __syncthreads();
    #pragma unroll
    for (int r = 0; r < 4; r++)
        g_mT[(size_t)(gb + ty + r * 8) * kN + nb + tx] = __float2half(t[tx][ty + r * 8]);
}

// ---------------- u = input^T @ sw ; cs = colsum(input) ; S = sum(sw) ----------------
__global__ void k_u(const float* __restrict__ inp, const float* __restrict__ sw) {
    int d  = blockIdx.x * 256 + threadIdx.x;
    int n0 = blockIdx.y * (kN / 32);
    float acc = 0.f, acc2 = 0.f;
    #pragma unroll 4
    for (int n = n0; n < n0 + kN / 32; n++) {
        float x = inp[(size_t)n * kD + d];
        acc += x * sw[n];
        acc2 += x;
    }
    atomicAdd(&g_u[d], acc);
    atomicAdd(&g_cs[d], acc2);
    if (blockIdx.x == 0) {
        __shared__ float red[256];
        red[threadIdx.x] = sw[n0 + threadIdx.x];
        __syncthreads();
        for (int s = 128; s > 0; s >>= 1) {
            if (threadIdx.x < s) red[threadIdx.x] += red[threadIdx.x + s];
            __syncthreads();
        }
        if (threadIdx.x == 0) atomicAdd(&g_S, red[0]);
    }
}

// ---------------- t = Wk @ u + bk * S ----------------
__global__ void k_t(const float* __restrict__ Wk, const float* __restrict__ bk) {
    int warp = threadIdx.x >> 5, lane = threadIdx.x & 31;
    int row = blockIdx.x * 8 + warp;
    const float* w = Wk + (size_t)row * kD;
    float acc = 0.f;
    #pragma unroll 8
    for (int k = lane; k < kD; k += 32) acc += w[k] * g_u[k];
    #pragma unroll
    for (int o = 16; o; o >>= 1) acc += __shfl_xor_sync(0xffffffffu, acc, o);
    if (lane == 0) g_t[row] = acc + bk[row] * g_S;
}

// ---------------- w2 = Wq^T @ t ; c = bq.t + score_b ----------------
__global__ void k_w2c(const float* __restrict__ Wq, const float* __restrict__ bq,
                      const float* __restrict__ score_b) {
    int b = blockIdx.x;                          // grid = 129
    if (b < 128) {
        int d  = (b & 3) * 256 + threadIdx.x;
        int h0 = (b >> 2) * 32;
        float acc = 0.f;
        #pragma unroll 4
        for (int h = h0; h < h0 + 32; h++)
            acc += Wq[(size_t)h * kD + d] * g_t[h];
        atomicAdd(&g_w2[d], acc);
    } else {
        __shared__ float red[256];
        float acc = 0.f;
        for (int h = threadIdx.x; h < kH; h += 256) acc += bq[h] * g_t[h];
        red[threadIdx.x] = acc;
        __syncthreads();
        for (int s = 128; s > 0; s >>= 1) {
            if (threadIdx.x < s) red[threadIdx.x] += red[threadIdx.x + s];
            __syncthreads();
        }
        if (threadIdx.x == 0) g_c = red[0] + score_b[0];
    }
}

// ---------------- s[n] = input[n,:].w2 + c ----------------
__global__ void k_s(const float* __restrict__ inp) {
    int warp = threadIdx.x >> 5, lane = threadIdx.x & 31;
    int row = blockIdx.x * 8 + warp;
    const float* r = inp + (size_t)row * kD;
    float acc = 0.f;
    #pragma unroll 8
    for (int k = lane; k < kD; k += 32) acc += r[k] * g_w2[k];
    #pragma unroll
    for (int o = 16; o; o >>= 1) acc += __shfl_xor_sync(0xffffffffu, acc, o);
    if (lane == 0) g_s[row] = acc + g_c;
}

// ---------------- e = exp(s - smax) ----------------
__global__ void k_e() {
    __shared__ float red[1024];
    __shared__ float smax;
    float m = -INFINITY;
    for (int i = threadIdx.x; i < kN; i += 1024) m = fmaxf(m, g_s[i]);
    red[threadIdx.x] = m;
    __syncthreads();
    for (int s = 512; s > 0; s >>= 1) {
        if (threadIdx.x < s) red[threadIdx.x] = fmaxf(red[threadIdx.x], red[threadIdx.x + s]);
        __syncthreads();
    }
    if (threadIdx.x == 0) smax = red[0];
    __syncthreads();
    float mx = smax;
    for (int i = threadIdx.x; i < kN; i += 1024) g_e[i] = expf(g_s[i] - mx);
}

// ---------------- vcs[h] = Wv[h,:].cs + N*bv[h] ----------------
__global__ void k_vcs(const float* __restrict__ Wv, const float* __restrict__ bv) {
    int warp = threadIdx.x >> 5, lane = threadIdx.x & 31;
    int row = blockIdx.x * 8 + warp;
    const float* w = Wv + (size_t)row * kD;
    float acc = 0.f;
    #pragma unroll 8
    for (int k = lane; k < kD; k += 32) acc += w[k] * g_cs[k];
    #pragma unroll
    for (int o = 16; o; o >>= 1) acc += __shfl_xor_sync(0xffffffffu, acc, o);
    if (lane == 0) g_vcs[row] = acc + (float)kN * bv[row];
}

// ================= GEMM 1: ve = e*(input @ Wv^T + bv), 3-term bf16, fp16 out =================
constexpr int V_STAGES = 3;
constexpr int V_TS = 128 * 40;
constexpr int V_STG_E = 4 * V_TS;
constexpr int V_SMEM = V_STAGES * V_STG_E * 2;  // 122880
constexpr int V_CHUNKS = kD / 32;               // 32

__global__ __launch_bounds__(256, 1) void k_v_mma(const float* __restrict__ bv) {
    __nv_bfloat16* sm = (__nv_bfloat16*)dynsmem;
    const int tid = threadIdx.x, lane = tid & 31, wid = tid >> 5;
    const int wm = (wid & 3) * 32, wn = (wid >> 2) * 64;
    const int n0 = blockIdx.x * 128;   // h tile
    const int m0 = blockIdx.y * 128;   // elem tile
    const int lrow = tid >> 1, lcol = (tid & 1) * 16;
    const uint32_t sbase = smem_u32(sm);

    const __nv_bfloat16* Ah = g_inh + (size_t)(m0 + lrow) * kD + lcol;
    const __nv_bfloat16* Al = g_inl + (size_t)(m0 + lrow) * kD + lcol;
    const __nv_bfloat16* Bh = g_wvh + (size_t)(n0 + lrow) * kD + lcol;
    const __nv_bfloat16* Bl = g_wvl + (size_t)(n0 + lrow) * kD + lcol;
    const uint32_t dst0 = sbase + (lrow * 40 + lcol) * 2;

    auto load_chunk = [&](int chunk, int stg) {
        uint32_t d = dst0 + stg * V_STG_E * 2;
        int ko = chunk * 32;
        cp_async16(d,                     Ah + ko);
        cp_async16(d + 16,                Ah + ko + 8);
        cp_async16(d + V_TS * 2,          Al + ko);
        cp_async16(d + V_TS * 2 + 16,     Al + ko + 8);
        cp_async16(d + 2 * V_TS * 2,      Bh + ko);
        cp_async16(d + 2 * V_TS * 2 + 16, Bh + ko + 8);
        cp_async16(d + 3 * V_TS * 2,      Bl + ko);
        cp_async16(d + 3 * V_TS * 2 + 16, Bl + ko + 8);
    };

    float acc[2][8][4];
    #pragma unroll
    for (int i = 0; i < 2; i++)
        #pragma unroll
        for (int j = 0; j < 8; j++)
            #pragma unroll
            for (int q = 0; q < 4; q++) acc[i][j][q] = 0.f;

    #pragma unroll
    for (int s = 0; s < V_STAGES - 1; ++s) { load_chunk(s, s); cp_commit(); }

    for (int i = 0; i < V_CHUNKS; ++i) {
        cp_wait<V_STAGES - 2>();
        __syncthreads();
        const int stg = i % V_STAGES;
        __nv_bfloat16 (*SAh)[40] = (__nv_bfloat16(*)[40])(sm + stg * V_STG_E);
        __nv_bfloat16 (*SAl)[40] = (__nv_bfloat16(*)[40])(sm + stg * V_STG_E + V_TS);
        __nv_bfloat16 (*SBh)[40] = (__nv_bfloat16(*)[40])(sm + stg * V_STG_E + 2 * V_TS);
        __nv_bfloat16 (*SBl)[40] = (__nv_bfloat16(*)[40])(sm + stg * V_STG_E + 3 * V_TS);
        #pragma unroll
        for (int kh = 0; kh < 2; kh++) {
            int kk = kh * 16;
            unsigned ah[2][4], al[2][4], bh[4][4], bl[4][4];
            #pragma unroll
            for (int im = 0; im < 2; im++) {
                ldsm4(ah[im][0], ah[im][1], ah[im][2], ah[im][3],
                      &SAh[wm + im * 16 + (lane & 15)][kk + (lane >> 4) * 8]);
                ldsm4(al[im][0], al[im][1], al[im][2], al[im][3],
                      &SAl[wm + im * 16 + (lane & 15)][kk + (lane >> 4) * 8]);
            }
            #pragma unroll
            for (int jn = 0; jn < 4; jn++) {
                ldsm4(bh[jn][0], bh[jn][1], bh[jn][2], bh[jn][3],
                      &SBh[wn + jn * 16 + (lane & 7) + ((lane >> 4) << 3)]
                          [kk + ((lane >> 3) & 1) * 8]);
                ldsm4(bl[jn][0], bl[jn][1], bl[jn][2], bl[jn][3],
                      &SBl[wn + jn * 16 + (lane & 7) + ((lane >> 4) << 3)]
                          [kk + ((lane >> 3) & 1) * 8]);
            }
            #pragma unroll
            for (int im = 0; im < 2; im++)
                #pragma unroll
                for (int j = 0; j < 8; j++) {
                    mma_bf16(acc[im][j], ah[im], bh[j >> 1][(j & 1) * 2],
                             bh[j >> 1][(j & 1) * 2 + 1]);
                    mma_bf16(acc[im][j], ah[im], bl[j >> 1][(j & 1) * 2],
                             bl[j >> 1][(j & 1) * 2 + 1]);
                    mma_bf16(acc[im][j], al[im], bh[j >> 1][(j & 1) * 2],
                             bh[j >> 1][(j & 1) * 2 + 1]);
                }
        }
        __syncthreads();
        int nx = i + V_STAGES - 1;
        if (nx < V_CHUNKS) load_chunk(nx, nx % V_STAGES);
        cp_commit();
    }

    // epilogue: add bias, scale by e[m], store single fp16
    const int gr = lane >> 2, gc = (lane & 3) * 2;
    #pragma unroll
    for (int im = 0; im < 2; im++) {
        #pragma unroll
        for (int r = 0; r < 2; r++) {
            int m = m0 + wm + im * 16 + gr + r * 8;
            float ev = g_e[m];
            #pragma unroll
            for (int j = 0; j < 8; j++) {
                int h = n0 + wn + j * 8 + gc;
                float x0 = (acc[im][j][r * 2 + 0] + bv[h])     * ev;
                float x1 = (acc[im][j][r * 2 + 1] + bv[h + 1]) * ev;
                __half2 o; o.x = __float2half(x0); o.y = __float2half(x1);
                *(__half2*)&g_vef[(size_t)m * kH + h] = o;
            }
        }
    }
}

// ================= GEMM 2: out = (mT @ vef) / Z, single fp16 term =================
constexpr int A_STAGES = 4;
constexpr int A_ATS = 128 * 40;                  // A tile: 128g x 32k (pad 40)
constexpr int A_BTS = 32 * 72;                   // B tile: 32k x 64h (pad 72)
constexpr int A_STG_E = A_ATS + A_BTS;           // 7424 elems
constexpr int A_SMEM = A_STAGES * A_STG_E * 2;   // 59392 bytes
constexpr int A_CHUNKS = kN / 32;                // 256

__global__ __launch_bounds__(256, 2) void k_agg_mma(float* __restrict__ out) {
    __half* sm = (__half*)dynsmem;
    const int tid = threadIdx.x, lane = tid & 31, wid = tid >> 5;
    const int wm = (wid & 3) * 32, wn = (wid >> 2) * 32;   // 4x2 warp grid
    const int h0 = blockIdx.x * 64;
    const int g0 = blockIdx.y * 128;
    const int lrow = tid >> 1, lcol = (tid & 1) * 16;   // A indices (128x32)
    const int brow = tid >> 3, bcol = (tid & 7) * 8;    // B indices (32x64)
    const uint32_t sbase = smem_u32(sm);

    const __half* Ag = g_mT  + (size_t)(g0 + lrow) * kN + lcol;
    const __half* Bp = g_vef + (size_t)brow * kH + h0 + bcol;
    const uint32_t adst0 = sbase + (lrow * 40 + lcol) * 2;
    const uint32_t bdst0 = sbase + A_ATS * 2 + (brow * 72 + bcol) * 2;

    auto load_chunk = [&](int chunk, int stg) {
        uint32_t ad = adst0 + stg * A_STG_E * 2;
        uint32_t bd = bdst0 + stg * A_STG_E * 2;
        int ko = chunk * 32;
        cp_async16(ad,      Ag + ko);
        cp_async16(ad + 16, Ag + ko + 8);
        cp_async16(bd, Bp + (size_t)ko * kH);
    };

    float acc[2][4][4];
    #pragma unroll
    for (int i = 0; i < 2; i++)
        #pragma unroll
        for (int j = 0; j < 4; j++)
            #pragma unroll
            for (int q = 0; q < 4; q++) acc[i][j][q] = 0.f;

    #pragma unroll
    for (int s = 0; s < A_STAGES - 1; ++s) { load_chunk(s, s); cp_commit(); }

    for (int i = 0; i < A_CHUNKS; ++i) {
        cp_wait<A_STAGES - 2>();
        __syncthreads();
        const int stg = i % A_STAGES;
        __half (*SA)[40] = (__half(*)[40])(sm + stg * A_STG_E);
        __half (*SB)[72] = (__half(*)[72])(sm + stg * A_STG_E + A_ATS);
        #pragma unroll
        for (int kh = 0; kh < 2; kh++) {
            int kk = kh * 16;
            unsigned a[2][4], b[2][4];
            #pragma unroll
            for (int im = 0; im < 2; im++)
                ldsm4(a[im][0], a[im][1], a[im][2], a[im][3],
                      &SA[wm + im * 16 + (lane & 15)][kk + (lane >> 4) * 8]);
            #pragma unroll
            for (int jn = 0; jn < 2; jn++)
                ldsm4t(b[jn][0], b[jn][1], b[jn][2], b[jn][3],
                       &SB[kk + (lane & 7) + ((lane >> 3) & 1) * 8]
                          [wn + jn * 16 + (lane >> 4) * 8]);
            #pragma unroll
            for (int im = 0; im < 2; im++)
                #pragma unroll
                for (int j = 0; j < 4; j++)
                    mma_f16(acc[im][j], a[im], b[j >> 1][(j & 1) * 2],
                            b[j >> 1][(j & 1) * 2 + 1]);
        }
        __syncthreads();
        int nx = i + A_STAGES - 1;
        if (nx < A_CHUNKS) load_chunk(nx, nx % A_STAGES);
        cp_commit();
    }

    // epilogue: divide by Z (or fallback)
    const int gr = lane >> 2, gc = (lane & 3) * 2;
    #pragma unroll
    for (int im = 0; im < 2; im++) {
        #pragma unroll
        for (int r = 0; r < 2; r++) {
            int g = g0 + wm + im * 16 + gr + r * 8;
            float Zv = g_Z[g];
            if (Zv > 0.f) {
                float rZ = 1.f / Zv;
                #pragma unroll
                for (int j = 0; j < 4; j++) {
                    int h = h0 + wn + j * 8 + gc;
                    float2 o;
                    o.x = acc[im][j][r * 2 + 0] * rZ;
                    o.y = acc[im][j][r * 2 + 1] * rZ;
                    *(float2*)&out[(size_t)g * kH + h] = o;
                }
            } else {
                const float invn = 1.f / (float)kN;
                #pragma unroll
                for (int j = 0; j < 4; j++) {
                    int h = h0 + wn + j * 8 + gc;
                    float2 o;
                    o.x = g_vcs[h] * invn;
                    o.y = g_vcs[h + 1] * invn;
                    *(float2*)&out[(size_t)g * kH + h] = o;
                }
            }
        }
    }
}

// ---------------- Z[g] = sum_n maskT[g,n]*e[n] ----------------
__global__ void k_Z2() {
    int g = blockIdx.x * 8 + (threadIdx.x >> 5);
    int lane = threadIdx.x & 31;
    const __half* mrow = g_mT + (size_t)g * kN;
    float acc = 0.f;
    for (int n = lane * 8; n < kN; n += 32 * 8) {
        uint4 mv = *(const uint4*)(mrow + n);
        float4 e0 = *(const float4*)(g_e + n);
        float4 e1 = *(const float4*)(g_e + n + 4);
        const __half2* mp = (const __half2*)&mv;
        float2 m0 = __half22float2(mp[0]);
        float2 m1 = __half22float2(mp[1]);
        float2 m2 = __half22float2(mp[2]);
        float2 m3 = __half22float2(mp[3]);
        acc += m0.x * e0.x + m0.y * e0.y + m1.x * e0.z + m1.y * e0.w
             + m2.x * e1.x + m2.y * e1.y + m3.x * e1.z + m3.y * e1.w;
    }
    #pragma unroll
    for (int o = 16; o; o >>= 1) acc += __shfl_xor_sync(0xffffffffu, acc, o);
    if (lane == 0) g_Z[g] = acc;
}

// ---------------- attn[g,n] = maskT[g,n]*e[n]/Z[g] (or 1/N fallback) ----------------
__global__ void k_attn2(float* __restrict__ attn) {
    int g = blockIdx.x;
    float Zv = g_Z[g];
    bool fb = !(Zv > 0.f);
    float rZ = fb ? 0.f : 1.f / Zv;
    const float invn = 1.f / (float)kN;
    const __half* mrow = g_mT + (size_t)g * kN;
    float* arow = attn + (size_t)g * kN;
    for (int n = threadIdx.x * 8; n < kN; n += 256 * 8) {
        uint4 mv = *(const uint4*)(mrow + n);
        float4 e0 = *(const float4*)(g_e + n);
        float4 e1 = *(const float4*)(g_e + n + 4);
        const __half2* mp = (const __half2*)&mv;
        float2 m0 = __half22float2(mp[0]);
        float2 m1 = __half22float2(mp[1]);
        float2 m2 = __half22float2(mp[2]);
        float2 m3 = __half22float2(mp[3]);
        float4 o0, o1;
        if (fb) {
            o0.x = o0.y = o0.z = o0.w = invn;
            o1 = o0;
        } else {
            o0.x = m0.x * e0.x * rZ; o0.y = m0.y * e0.y * rZ;
            o0.z = m1.x * e0.z * rZ; o0.w = m1.y * e0.w * rZ;
            o1.x = m2.x * e1.x * rZ; o1.y = m2.y * e1.y * rZ;
            o1.z = m3.x * e1.z * rZ; o1.w = m3.y * e1.w * rZ;
        }
        *(float4*)(arow + n)     = o0;
        *(float4*)(arow + n + 4) = o1;
    }
}

// ---------------- host launcher (multi-stream graph branches) ----------------
extern "C" void kernel_launch(void* const* d_in, const int* in_sizes, int n_in,
                              void* d_out, int out_size) {
    const float* input = (const float*)d_in[0];
    const float* Wq    = (const float*)d_in[1];
    const float* bq    = (const float*)d_in[2];
    const float* Wk    = (const float*)d_in[3];
    const float* bk    = (const float*)d_in[4];
    const float* Wv    = (const float*)d_in[5];
    const float* bv    = (const float*)d_in[6];
    const float* sw    = (const float*)d_in[7];
    const float* sb    = (const float*)d_in[8];
    const int*   mask  = (const int*)d_in[9];
    float* out = (float*)d_out;

    __nv_bfloat16 *inh, *inl, *wvh, *wvl;
    cudaGetSymbolAddress((void**)&inh, g_inh);
    cudaGetSymbolAddress((void**)&inl, g_inl);
    cudaGetSymbolAddress((void**)&wvh, g_wvh);
    cudaGetSymbolAddress((void**)&wvl, g_wvl);

    static cudaStream_t s1 = nullptr, s2 = nullptr;
    static cudaEvent_t evF, ev1, evZ;
    if (!s1) {
        cudaStreamCreateWithFlags(&s1, cudaStreamNonBlocking);
        cudaStreamCreateWithFlags(&s2, cudaStreamNonBlocking);
        cudaEventCreateWithFlags(&evF, cudaEventDisableTiming);
        cudaEventCreateWithFlags(&ev1, cudaEventDisableTiming);
        cudaEventCreateWithFlags(&evZ, cudaEventDisableTiming);
        cudaFuncSetAttribute(k_v_mma, cudaFuncAttributeMaxDynamicSharedMemorySize, V_SMEM);
        cudaFuncSetAttribute(k_agg_mma, cudaFuncAttributeMaxDynamicSharedMemorySize, A_SMEM);
    }

    k_init<<<8, 256>>>();
    cudaEventRecord(evF, 0);
    cudaStreamWaitEvent(s1, evF, 0);
    cudaStreamWaitEvent(s2, evF, 0);

    // s1: scalar score chain
    k_u<<<dim3(4, 32), 256, 0, s1>>>(input, sw);
    k_t<<<128, 256, 0, s1>>>(Wk, bk);
    k_w2c<<<129, 256, 0, s1>>>(Wq, bq, sb);
    k_s<<<1024, 256, 0, s1>>>(input);
    k_e<<<1, 1024, 0, s1>>>();
    k_vcs<<<128, 256, 0, s1>>>(Wv, bv);
    cudaEventRecord(ev1, s1);

    // s2: mask transpose, then Z + attention weights (overlap with k_v_mma)
    k_maskT<<<dim3(kG / 32, kN / 32), dim3(32, 8), 0, s2>>>(mask);
    cudaStreamWaitEvent(s2, ev1, 0);                 // needs g_e
    k_Z2<<<kG / 8, 256, 0, s2>>>();
    k_attn2<<<kG, 256, 0, s2>>>(out + (size_t)kG * kH);
    cudaEventRecord(evZ, s2);

    // main: splits, then GEMMs
    k_split<<<(kN * kD) / 1024, 256>>>((const float4*)input, inh, inl);
    k_split<<<(kH * kD) / 1024, 256>>>((const float4*)Wv, wvh, wvl);
    cudaStreamWaitEvent(0, ev1, 0);                  // needs g_e, g_vcs
    k_v_mma<<<dim3(kH / 128, kN / 128), 256, V_SMEM>>>(bv);
    cudaStreamWaitEvent(0, evZ, 0);                  // needs g_mT, g_Z (joins s2)
    k_agg_mma<<<dim3(kH / 64, kG / 128), 256, A_SMEM>>>(out);
}

// round 8
// speedup vs baseline: 1.8442x; 1.5170x over previous
#include <cuda_runtime.h>
#include <cuda_bf16.h>
#include <cuda_fp16.h>
#include <math.h>
#include <cstdint>

constexpr int kN = 8192;   // num_elem
constexpr int kD = 1024;   // input_size
constexpr int kH = 1024;   // hidden_size
constexpr int kG = 2048;   // num_groups

// ---------------- device scratch ----------------
__device__ float g_u[kD];
__device__ float g_cs[kD];
__device__ float g_S;
__device__ float g_t[kH];
__device__ float g_w2[kD];
__device__ float g_c;
__device__ float g_s[kN];
__device__ float g_e[kN];
__device__ float g_vcs[kH];
__device__ float g_Z[kG];
__device__ __half g_inf[(size_t)kN * kD];          // input fp16       [n][d]
__device__ __nv_bfloat16 g_wvh[(size_t)kH * kD];   // Wv hi            [h][d]
__device__ __nv_bfloat16 g_wvl[(size_t)kH * kD];   // Wv lo
__device__ __half g_mT[(size_t)kG * kN];           // mask^T 0/1 fp16  [g][n]
__device__ __half g_me[(size_t)kG * kN];           // mask^T * e fp16  [g][n]
__device__ __nv_bfloat16 g_ph[(size_t)kG * kD];    // P = me@input, hi [g][d]
__device__ __nv_bfloat16 g_pl[(size_t)kG * kD];    // P lo

// ---------------- mma helpers ----------------
__device__ __forceinline__ void ldsm4(unsigned& r0, unsigned& r1, unsigned& r2, unsigned& r3,
                                      const void* p) {
    unsigned a = (unsigned)__cvta_generic_to_shared(p);
    asm volatile("ldmatrix.sync.aligned.m8n8.x4.shared.b16 {%0,%1,%2,%3}, [%4];"
                 : "=r"(r0), "=r"(r1), "=r"(r2), "=r"(r3) : "r"(a));
}
__device__ __forceinline__ void ldsm4t(unsigned& r0, unsigned& r1, unsigned& r2, unsigned& r3,
                                       const void* p) {
    unsigned a = (unsigned)__cvta_generic_to_shared(p);
    asm volatile("ldmatrix.sync.aligned.m8n8.x4.trans.shared.b16 {%0,%1,%2,%3}, [%4];"
                 : "=r"(r0), "=r"(r1), "=r"(r2), "=r"(r3) : "r"(a));
}
__device__ __forceinline__ void mma_bf16(float* c, const unsigned* a, unsigned b0, unsigned b1) {
    asm volatile("mma.sync.aligned.m16n8k16.row.col.f32.bf16.bf16.f32 "
                 "{%0,%1,%2,%3},{%4,%5,%6,%7},{%8,%9},{%0,%1,%2,%3};"
                 : "+f"(c[0]), "+f"(c[1]), "+f"(c[2]), "+f"(c[3])
                 : "r"(a[0]), "r"(a[1]), "r"(a[2]), "r"(a[3]), "r"(b0), "r"(b1));
}
__device__ __forceinline__ void mma_f16(float* c, const unsigned* a, unsigned b0, unsigned b1) {
    asm volatile("mma.sync.aligned.m16n8k16.row.col.f32.f16.f16.f32 "
                 "{%0,%1,%2,%3},{%4,%5,%6,%7},{%8,%9},{%0,%1,%2,%3};"
                 : "+f"(c[0]), "+f"(c[1]), "+f"(c[2]), "+f"(c[3])
                 : "r"(a[0]), "r"(a[1]), "r"(a[2]), "r"(a[3]), "r"(b0), "r"(b1));
}
__device__ __forceinline__ void cp_async16(uint32_t dst, const void* src) {
    asm volatile("cp.async.cg.shared.global [%0], [%1], 16;" :: "r"(dst), "l"(src) : "memory");
}
__device__ __forceinline__ void cp_commit() {
    asm volatile("cp.async.commit_group;" ::: "memory");
}
template <int Nn>
__device__ __forceinline__ void cp_wait() {
    asm volatile("cp.async.wait_group %0;" :: "n"(Nn) : "memory");
}
__device__ __forceinline__ uint32_t smem_u32(const void* p) {
    return (uint32_t)__cvta_generic_to_shared(p);
}

extern __shared__ __align__(128) char dynsmem[];

// ---------------- init ----------------
__global__ void k_init() {
    int idx = blockIdx.x * 256 + threadIdx.x;
    if (idx < kD) { g_u[idx] = 0.f; g_w2[idx] = 0.f; g_cs[idx] = 0.f; }
    if (idx < kG) g_Z[idx] = 0.f;
    if (idx == 0) g_S = 0.f;
}

// ---------------- fp32 -> bf16 hi/lo split (Wv) ----------------
__global__ void k_split(const float4* __restrict__ src, __nv_bfloat16* __restrict__ hi,
                        __nv_bfloat16* __restrict__ lo) {
    size_t i = (size_t)blockIdx.x * 256 + threadIdx.x;
    float4 x = src[i];
    __nv_bfloat16 h0 = __float2bfloat16(x.x), h1 = __float2bfloat16(x.y);
    __nv_bfloat16 h2 = __float2bfloat16(x.z), h3 = __float2bfloat16(x.w);
    __nv_bfloat162 hv0; hv0.x = h0; hv0.y = h1;
    __nv_bfloat162 hv1; hv1.x = h2; hv1.y = h3;
    __nv_bfloat162 lv0, lv1;
    lv0.x = __float2bfloat16(x.x - __bfloat162float(h0));
    lv0.y = __float2bfloat16(x.y - __bfloat162float(h1));
    lv1.x = __float2bfloat16(x.z - __bfloat162float(h2));
    lv1.y = __float2bfloat16(x.w - __bfloat162float(h3));
    *(__nv_bfloat162*)(hi + 4 * i)     = hv0;
    *(__nv_bfloat162*)(hi + 4 * i + 2) = hv1;
    *(__nv_bfloat162*)(lo + 4 * i)     = lv0;
    *(__nv_bfloat162*)(lo + 4 * i + 2) = lv1;
}

// ---------------- fp32 -> fp16 (input) ----------------
__global__ void k_splitf(const float4* __restrict__ src, __half* __restrict__ dst) {
    size_t i = (size_t)blockIdx.x * 256 + threadIdx.x;
    float4 x = src[i];
    __half2 a; a.x = __float2half(x.x); a.y = __float2half(x.y);
    __half2 b; b.x = __float2half(x.z); b.y = __float2half(x.w);
    *(__half2*)(dst + 4 * i)     = a;
    *(__half2*)(dst + 4 * i + 2) = b;
}

// ---------------- transpose mask -> mT (0/1) and me = m*e, both fp16 ----------------
__global__ void k_meT(const int* __restrict__ mask) {
    __shared__ float t[32][33];
    int gb = blockIdx.x * 32, nb = blockIdx.y * 32;
    int tx = threadIdx.x, ty = threadIdx.y;     // (32,8)
    #pragma unroll
    for (int r = 0; r < 4; r++)
        t[ty + r * 8][tx] = mask[(size_t)(nb + ty + r * 8) * kG + gb + tx] ? 1.f : 0.f;
    __syncthreads();
    float ev = g_e[nb + tx];
    #pragma unroll
    for (int r = 0; r < 4; r++) {
        float mv = t[tx][ty + r * 8];
        size_t idx = (size_t)(gb + ty + r * 8) * kN + nb + tx;
        g_mT[idx] = __float2half(mv);
        g_me[idx] = __float2half(mv * ev);
    }
}

// ---------------- u = input^T @ sw ; cs = colsum(input) ; S = sum(sw) ----------------
__global__ void k_u(const float* __restrict__ inp, const float* __restrict__ sw) {
    int d  = blockIdx.x * 256 + threadIdx.x;
    int n0 = blockIdx.y * (kN / 32);
    float acc = 0.f, acc2 = 0.f;
    #pragma unroll 4
    for (int n = n0; n < n0 + kN / 32; n++) {
        float x = inp[(size_t)n * kD + d];
        acc += x * sw[n];
        acc2 += x;
    }
    atomicAdd(&g_u[d], acc);
    atomicAdd(&g_cs[d], acc2);
    if (blockIdx.x == 0) {
        __shared__ float red[256];
        red[threadIdx.x] = sw[n0 + threadIdx.x];
        __syncthreads();
        for (int s = 128; s > 0; s >>= 1) {
            if (threadIdx.x < s) red[threadIdx.x] += red[threadIdx.x + s];
            __syncthreads();
        }
        if (threadIdx.x == 0) atomicAdd(&g_S, red[0]);
    }
}

// ---------------- t = Wk @ u + bk * S ----------------
__global__ void k_t(const float* __restrict__ Wk, const float* __restrict__ bk) {
    int warp = threadIdx.x >> 5, lane = threadIdx.x & 31;
    int row = blockIdx.x * 8 + warp;
    const float* w = Wk + (size_t)row * kD;
    float acc = 0.f;
    #pragma unroll 8
    for (int k = lane; k < kD; k += 32) acc += w[k] * g_u[k];
    #pragma unroll
    for (int o = 16; o; o >>= 1) acc += __shfl_xor_sync(0xffffffffu, acc, o);
    if (lane == 0) g_t[row] = acc + bk[row] * g_S;
}

// ---------------- w2 = Wq^T @ t ; c = bq.t + score_b ----------------
__global__ void k_w2c(const float* __restrict__ Wq, const float* __restrict__ bq,
                      const float* __restrict__ score_b) {
    int b = blockIdx.x;                          // grid = 129
    if (b < 128) {
        int d  = (b & 3) * 256 + threadIdx.x;
        int h0 = (b >> 2) * 32;
        float acc = 0.f;
        #pragma unroll 4
        for (int h = h0; h < h0 + 32; h++)
            acc += Wq[(size_t)h * kD + d] * g_t[h];
        atomicAdd(&g_w2[d], acc);
    } else {
        __shared__ float red[256];
        float acc = 0.f;
        for (int h = threadIdx.x; h < kH; h += 256) acc += bq[h] * g_t[h];
        red[threadIdx.x] = acc;
        __syncthreads();
        for (int s = 128; s > 0; s >>= 1) {
            if (threadIdx.x < s) red[threadIdx.x] += red[threadIdx.x + s];
            __syncthreads();
        }
        if (threadIdx.x == 0) g_c = red[0] + score_b[0];
    }
}

// ---------------- s[n] = input[n,:].w2 + c ----------------
__global__ void k_s(const float* __restrict__ inp) {
    int warp = threadIdx.x >> 5, lane = threadIdx.x & 31;
    int row = blockIdx.x * 8 + warp;
    const float* r = inp + (size_t)row * kD;
    float acc = 0.f;
    #pragma unroll 8
    for (int k = lane; k < kD; k += 32) acc += r[k] * g_w2[k];
    #pragma unroll
    for (int o = 16; o; o >>= 1) acc += __shfl_xor_sync(0xffffffffu, acc, o);
    if (lane == 0) g_s[row] = acc + g_c;
}

// ---------------- e = exp(s - smax) ----------------
__global__ void k_e() {
    __shared__ float red[1024];
    __shared__ float smax;
    float m = -INFINITY;
    for (int i = threadIdx.x; i < kN; i += 1024) m = fmaxf(m, g_s[i]);
    red[threadIdx.x] = m;
    __syncthreads();
    for (int s = 512; s > 0; s >>= 1) {
        if (threadIdx.x < s) red[threadIdx.x] = fmaxf(red[threadIdx.x], red[threadIdx.x + s]);
        __syncthreads();
    }
    if (threadIdx.x == 0) smax = red[0];
    __syncthreads();
    float mx = smax;
    for (int i = threadIdx.x; i < kN; i += 1024) g_e[i] = expf(g_s[i] - mx);
}

// ---------------- vcs[h] = Wv[h,:].cs + N*bv[h] ----------------
__global__ void k_vcs(const float* __restrict__ Wv, const float* __restrict__ bv) {
    int warp = threadIdx.x >> 5, lane = threadIdx.x & 31;
    int row = blockIdx.x * 8 + warp;
    const float* w = Wv + (size_t)row * kD;
    float acc = 0.f;
    #pragma unroll 8
    for (int k = lane; k < kD; k += 32) acc += w[k] * g_cs[k];
    #pragma unroll
    for (int o = 16; o; o >>= 1) acc += __shfl_xor_sync(0xffffffffu, acc, o);
    if (lane == 0) g_vcs[row] = acc + (float)kN * bv[row];
}

// ================= Stage 1: P[G,D] = me @ input (fp16 mma), split-store bf16 =================
constexpr int A_STAGES = 4;
constexpr int A_ATS = 128 * 40;                  // A tile: 128g x 32k (pad 40)
constexpr int A_BTS = 32 * 72;                   // B tile: 32k x 64d (pad 72)
constexpr int A_STG_E = A_ATS + A_BTS;           // 7424 elems
constexpr int A_SMEM = A_STAGES * A_STG_E * 2;   // 59392 bytes
constexpr int A_CHUNKS = kN / 32;                // 256

__global__ __launch_bounds__(256, 2) void k_p_mma() {
    __half* sm = (__half*)dynsmem;
    const int tid = threadIdx.x, lane = tid & 31, wid = tid >> 5;
    const int wm = (wid & 3) * 32, wn = (wid >> 2) * 32;   // 4x2 warp grid
    const int d0 = blockIdx.x * 64;
    const int g0 = blockIdx.y * 128;
    const int lrow = tid >> 1, lcol = (tid & 1) * 16;   // A indices (128x32)
    const int brow = tid >> 3, bcol = (tid & 7) * 8;    // B indices (32x64)
    const uint32_t sbase = smem_u32(sm);

    const __half* Ag = g_me  + (size_t)(g0 + lrow) * kN + lcol;
    const __half* Bp = g_inf + (size_t)brow * kD + d0 + bcol;
    const uint32_t adst0 = sbase + (lrow * 40 + lcol) * 2;
    const uint32_t bdst0 = sbase + A_ATS * 2 + (brow * 72 + bcol) * 2;

    auto load_chunk = [&](int chunk, int stg) {
        uint32_t ad = adst0 + stg * A_STG_E * 2;
        uint32_t bd = bdst0 + stg * A_STG_E * 2;
        int ko = chunk * 32;
        cp_async16(ad,      Ag + ko);
        cp_async16(ad + 16, Ag + ko + 8);
        cp_async16(bd, Bp + (size_t)ko * kD);
    };

    float acc[2][4][4];
    #pragma unroll
    for (int i = 0; i < 2; i++)
        #pragma unroll
        for (int j = 0; j < 4; j++)
            #pragma unroll
            for (int q = 0; q < 4; q++) acc[i][j][q] = 0.f;

    #pragma unroll
    for (int s = 0; s < A_STAGES - 1; ++s) { load_chunk(s, s); cp_commit(); }

    for (int i = 0; i < A_CHUNKS; ++i) {
        cp_wait<A_STAGES - 2>();
        __syncthreads();
        const int stg = i % A_STAGES;
        __half (*SA)[40] = (__half(*)[40])(sm + stg * A_STG_E);
        __half (*SB)[72] = (__half(*)[72])(sm + stg * A_STG_E + A_ATS);
        #pragma unroll
        for (int kh = 0; kh < 2; kh++) {
            int kk = kh * 16;
            unsigned a[2][4], b[2][4];
            #pragma unroll
            for (int im = 0; im < 2; im++)
                ldsm4(a[im][0], a[im][1], a[im][2], a[im][3],
                      &SA[wm + im * 16 + (lane & 15)][kk + (lane >> 4) * 8]);
            #pragma unroll
            for (int jn = 0; jn < 2; jn++)
                ldsm4t(b[jn][0], b[jn][1], b[jn][2], b[jn][3],
                       &SB[kk + (lane & 7) + ((lane >> 3) & 1) * 8]
                          [wn + jn * 16 + (lane >> 4) * 8]);
            #pragma unroll
            for (int im = 0; im < 2; im++)
                #pragma unroll
                for (int j = 0; j < 4; j++)
                    mma_f16(acc[im][j], a[im], b[j >> 1][(j & 1) * 2],
                            b[j >> 1][(j & 1) * 2 + 1]);
        }
        __syncthreads();
        int nx = i + A_STAGES - 1;
        if (nx < A_CHUNKS) load_chunk(nx, nx % A_STAGES);
        cp_commit();
    }

    // epilogue: split-store P to bf16 hi/lo
    const int gr = lane >> 2, gc = (lane & 3) * 2;
    #pragma unroll
    for (int im = 0; im < 2; im++) {
        #pragma unroll
        for (int r = 0; r < 2; r++) {
            int g = g0 + wm + im * 16 + gr + r * 8;
            #pragma unroll
            for (int j = 0; j < 4; j++) {
                int d = d0 + wn + j * 8 + gc;
                float x0 = acc[im][j][r * 2 + 0];
                float x1 = acc[im][j][r * 2 + 1];
                __nv_bfloat16 h0 = __float2bfloat16(x0);
                __nv_bfloat16 h1 = __float2bfloat16(x1);
                __nv_bfloat162 hv; hv.x = h0; hv.y = h1;
                __nv_bfloat162 lv;
                lv.x = __float2bfloat16(x0 - __bfloat162float(h0));
                lv.y = __float2bfloat16(x1 - __bfloat162float(h1));
                *(__nv_bfloat162*)&g_ph[(size_t)g * kD + d] = hv;
                *(__nv_bfloat162*)&g_pl[(size_t)g * kD + d] = lv;
            }
        }
    }
}

// ================= Stage 2: out = (P @ Wv^T)/Z + bv, 3-term bf16 =================
constexpr int V_STAGES = 3;
constexpr int V_TS = 128 * 40;
constexpr int V_STG_E = 4 * V_TS;                // Ph, Pl, Wh, Wl
constexpr int V_SMEM = V_STAGES * V_STG_E * 2;   // 122880
constexpr int V_CHUNKS = kD / 32;                // 32

__global__ __launch_bounds__(256, 1) void k_out_mma(const float* __restrict__ bv,
                                                    float* __restrict__ out) {
    __nv_bfloat16* sm = (__nv_bfloat16*)dynsmem;
    const int tid = threadIdx.x, lane = tid & 31, wid = tid >> 5;
    const int wm = (wid & 3) * 32, wn = (wid >> 2) * 64;
    const int n0 = blockIdx.x * 128;   // h tile
    const int g0 = blockIdx.y * 128;   // group tile
    const int lrow = tid >> 1, lcol = (tid & 1) * 16;
    const uint32_t sbase = smem_u32(sm);

    const __nv_bfloat16* Ph = g_ph  + (size_t)(g0 + lrow) * kD + lcol;
    const __nv_bfloat16* Pl = g_pl  + (size_t)(g0 + lrow) * kD + lcol;
    const __nv_bfloat16* Wh = g_wvh + (size_t)(n0 + lrow) * kD + lcol;
    const __nv_bfloat16* Wl = g_wvl + (size_t)(n0 + lrow) * kD + lcol;
    const uint32_t dst0 = sbase + (lrow * 40 + lcol) * 2;

    auto load_chunk = [&](int chunk, int stg) {
        uint32_t d = dst0 + stg * V_STG_E * 2;
        int ko = chunk * 32;
        cp_async16(d,                     Ph + ko);
        cp_async16(d + 16,                Ph + ko + 8);
        cp_async16(d + V_TS * 2,          Pl + ko);
        cp_async16(d + V_TS * 2 + 16,     Pl + ko + 8);
        cp_async16(d + 2 * V_TS * 2,      Wh + ko);
        cp_async16(d + 2 * V_TS * 2 + 16, Wh + ko + 8);
        cp_async16(d + 3 * V_TS * 2,      Wl + ko);
        cp_async16(d + 3 * V_TS * 2 + 16, Wl + ko + 8);
    };

    float acc[2][8][4];
    #pragma unroll
    for (int i = 0; i < 2; i++)
        #pragma unroll
        for (int j = 0; j < 8; j++)
            #pragma unroll
            for (int q = 0; q < 4; q++) acc[i][j][q] = 0.f;

    #pragma unroll
    for (int s = 0; s < V_STAGES - 1; ++s) { load_chunk(s, s); cp_commit(); }

    for (int i = 0; i < V_CHUNKS; ++i) {
        cp_wait<V_STAGES - 2>();
        __syncthreads();
        const int stg = i % V_STAGES;
        __nv_bfloat16 (*SPh)[40] = (__nv_bfloat16(*)[40])(sm + stg * V_STG_E);
        __nv_bfloat16 (*SPl)[40] = (__nv_bfloat16(*)[40])(sm + stg * V_STG_E + V_TS);
        __nv_bfloat16 (*SWh)[40] = (__nv_bfloat16(*)[40])(sm + stg * V_STG_E + 2 * V_TS);
        __nv_bfloat16 (*SWl)[40] = (__nv_bfloat16(*)[40])(sm + stg * V_STG_E + 3 * V_TS);
        #pragma unroll
        for (int kh = 0; kh < 2; kh++) {
            int kk = kh * 16;
            unsigned ah[2][4], al[2][4], bh[4][4], bl[4][4];
            #pragma unroll
            for (int im = 0; im < 2; im++) {
                ldsm4(ah[im][0], ah[im][1], ah[im][2], ah[im][3],
                      &SPh[wm + im * 16 + (lane & 15)][kk + (lane >> 4) * 8]);
                ldsm4(al[im][0], al[im][1], al[im][2], al[im][3],
                      &SPl[wm + im * 16 + (lane & 15)][kk + (lane >> 4) * 8]);
            }
            #pragma unroll
            for (int jn = 0; jn < 4; jn++) {
                ldsm4(bh[jn][0], bh[jn][1], bh[jn][2], bh[jn][3],
                      &SWh[wn + jn * 16 + (lane & 7) + ((lane >> 4) << 3)]
                          [kk + ((lane >> 3) & 1) * 8]);
                ldsm4(bl[jn][0], bl[jn][1], bl[jn][2], bl[jn][3],
                      &SWl[wn + jn * 16 + (lane & 7) + ((lane >> 4) << 3)]
                          [kk + ((lane >> 3) & 1) * 8]);
            }
            #pragma unroll
            for (int im = 0; im < 2; im++)
                #pragma unroll
                for (int j = 0; j < 8; j++) {
                    mma_bf16(acc[im][j], ah[im], bh[j >> 1][(j & 1) * 2],
                             bh[j >> 1][(j & 1) * 2 + 1]);
                    mma_bf16(acc[im][j], ah[im], bl[j >> 1][(j & 1) * 2],
                             bl[j >> 1][(j & 1) * 2 + 1]);
                    mma_bf16(acc[im][j], al[im], bh[j >> 1][(j & 1) * 2],
                             bh[j >> 1][(j & 1) * 2 + 1]);
                }
        }
        __syncthreads();
        int nx = i + V_STAGES - 1;
        if (nx < V_CHUNKS) load_chunk(nx, nx % V_STAGES);
        cp_commit();
    }

    // epilogue: out = acc/Z + bv, or vcs/N fallback
    const int gr = lane >> 2, gc = (lane & 3) * 2;
    #pragma unroll
    for (int im = 0; im < 2; im++) {
        #pragma unroll
        for (int r = 0; r < 2; r++) {
            int g = g0 + wm + im * 16 + gr + r * 8;
            float Zv = g_Z[g];
            if (Zv > 0.f) {
                float rZ = 1.f / Zv;
                #pragma unroll
                for (int j = 0; j < 8; j++) {
                    int h = n0 + wn + j * 8 + gc;
                    float2 o;
                    o.x = acc[im][j][r * 2 + 0] * rZ + bv[h];
                    o.y = acc[im][j][r * 2 + 1] * rZ + bv[h + 1];
                    *(float2*)&out[(size_t)g * kH + h] = o;
                }
            } else {
                const float invn = 1.f / (float)kN;
                #pragma unroll
                for (int j = 0; j < 8; j++) {
                    int h = n0 + wn + j * 8 + gc;
                    float2 o;
                    o.x = g_vcs[h] * invn;
                    o.y = g_vcs[h + 1] * invn;
                    *(float2*)&out[(size_t)g * kH + h] = o;
                }
            }
        }
    }
}

// ---------------- Z[g] = sum_n mT[g,n]*e[n] (exact fp32) ----------------
__global__ void k_Z2() {
    int g = blockIdx.x * 8 + (threadIdx.x >> 5);
    int lane = threadIdx.x & 31;
    const __half* mrow = g_mT + (size_t)g * kN;
    float acc = 0.f;
    for (int n = lane * 8; n < kN; n += 32 * 8) {
        uint4 mv = *(const uint4*)(mrow + n);
        float4 e0 = *(const float4*)(g_e + n);
        float4 e1 = *(const float4*)(g_e + n + 4);
        const __half2* mp = (const __half2*)&mv;
        float2 m0 = __half22float2(mp[0]);
        float2 m1 = __half22float2(mp[1]);
        float2 m2 = __half22float2(mp[2]);
        float2 m3 = __half22float2(mp[3]);
        acc += m0.x * e0.x + m0.y * e0.y + m1.x * e0.z + m1.y * e0.w
             + m2.x * e1.x + m2.y * e1.y + m3.x * e1.z + m3.y * e1.w;
    }
    #pragma unroll
    for (int o = 16; o; o >>= 1) acc += __shfl_xor_sync(0xffffffffu, acc, o);
    if (lane == 0) g_Z[g] = acc;
}

// ---------------- attn[g,n] = mT[g,n]*e[n]/Z[g] (or 1/N fallback) ----------------
__global__ void k_attn2(float* __restrict__ attn) {
    int g = blockIdx.x;
    float Zv = g_Z[g];
    bool fb = !(Zv > 0.f);
    float rZ = fb ? 0.f : 1.f / Zv;
    const float invn = 1.f / (float)kN;
    const __half* mrow = g_mT + (size_t)g * kN;
    float* arow = attn + (size_t)g * kN;
    for (int n = threadIdx.x * 8; n < kN; n += 256 * 8) {
        uint4 mv = *(const uint4*)(mrow + n);
        float4 e0 = *(const float4*)(g_e + n);
        float4 e1 = *(const float4*)(g_e + n + 4);
        const __half2* mp = (const __half2*)&mv;
        float2 m0 = __half22float2(mp[0]);
        float2 m1 = __half22float2(mp[1]);
        float2 m2 = __half22float2(mp[2]);
        float2 m3 = __half22float2(mp[3]);
        float4 o0, o1;
        if (fb) {
            o0.x = o0.y = o0.z = o0.w = invn;
            o1 = o0;
        } else {
            o0.x = m0.x * e0.x * rZ; o0.y = m0.y * e0.y * rZ;
            o0.z = m1.x * e0.z * rZ; o0.w = m1.y * e0.w * rZ;
            o1.x = m2.x * e1.x * rZ; o1.y = m2.y * e1.y * rZ;
            o1.z = m3.x * e1.z * rZ; o1.w = m3.y * e1.w * rZ;
        }
        *(float4*)(arow + n)     = o0;
        *(float4*)(arow + n + 4) = o1;
    }
}

// ---------------- host launcher (multi-stream graph branches) ----------------
extern "C" void kernel_launch(void* const* d_in, const int* in_sizes, int n_in,
                              void* d_out, int out_size) {
    const float* input = (const float*)d_in[0];
    const float* Wq    = (const float*)d_in[1];
    const float* bq    = (const float*)d_in[2];
    const float* Wk    = (const float*)d_in[3];
    const float* bk    = (const float*)d_in[4];
    const float* Wv    = (const float*)d_in[5];
    const float* bv    = (const float*)d_in[6];
    const float* sw    = (const float*)d_in[7];
    const float* sb    = (const float*)d_in[8];
    const int*   mask  = (const int*)d_in[9];
    float* out = (float*)d_out;

    __half* inf;
    __nv_bfloat16 *wvh, *wvl;
    cudaGetSymbolAddress((void**)&inf, g_inf);
    cudaGetSymbolAddress((void**)&wvh, g_wvh);
    cudaGetSymbolAddress((void**)&wvl, g_wvl);

    static cudaStream_t s1 = nullptr, s2 = nullptr;
    static cudaEvent_t evF, ev1, evME, evZ;
    if (!s1) {
        cudaStreamCreateWithFlags(&s1, cudaStreamNonBlocking);
        cudaStreamCreateWithFlags(&s2, cudaStreamNonBlocking);
        cudaEventCreateWithFlags(&evF, cudaEventDisableTiming);
        cudaEventCreateWithFlags(&ev1, cudaEventDisableTiming);
        cudaEventCreateWithFlags(&evME, cudaEventDisableTiming);
        cudaEventCreateWithFlags(&evZ, cudaEventDisableTiming);
        cudaFuncSetAttribute(k_p_mma, cudaFuncAttributeMaxDynamicSharedMemorySize, A_SMEM);
        cudaFuncSetAttribute(k_out_mma, cudaFuncAttributeMaxDynamicSharedMemorySize, V_SMEM);
    }

    k_init<<<8, 256>>>();
    cudaEventRecord(evF, 0);
    cudaStreamWaitEvent(s1, evF, 0);
    cudaStreamWaitEvent(s2, evF, 0);

    // s1: scalar score chain -> e, vcs
    k_u<<<dim3(4, 32), 256, 0, s1>>>(input, sw);
    k_t<<<128, 256, 0, s1>>>(Wk, bk);
    k_w2c<<<129, 256, 0, s1>>>(Wq, bq, sb);
    k_s<<<1024, 256, 0, s1>>>(input);
    k_e<<<1, 1024, 0, s1>>>();
    k_vcs<<<128, 256, 0, s1>>>(Wv, bv);
    cudaEventRecord(ev1, s1);

    // s2: mT + me (needs e), then Z + attention weights (overlap with k_p_mma)
    cudaStreamWaitEvent(s2, ev1, 0);
    k_meT<<<dim3(kG / 32, kN / 32), dim3(32, 8), 0, s2>>>(mask);
    cudaEventRecord(evME, s2);
    k_Z2<<<kG / 8, 256, 0, s2>>>();
    k_attn2<<<kG, 256, 0, s2>>>(out + (size_t)kG * kH);
    cudaEventRecord(evZ, s2);

    // main: conversions, then the two GEMM stages
    k_splitf<<<(kN * kD) / 1024, 256>>>((const float4*)input, inf);
    k_split<<<(kH * kD) / 1024, 256>>>((const float4*)Wv, wvh, wvl);
    cudaStreamWaitEvent(0, evME, 0);                 // needs g_me
    k_p_mma<<<dim3(kD / 64, kG / 128), 256, A_SMEM>>>();
    cudaStreamWaitEvent(0, evZ, 0);                  // needs g_Z (joins s2)
    k_out_mma<<<dim3(kH / 128, kG / 128), 256, V_SMEM>>>(bv, out);
}